// round 17
// baseline (speedup 1.0000x reference)
#include <cuda_runtime.h>
#include <cuda_fp16.h>
#include <cstdint>

// ---------------------------------------------------------------------------
// B=2,S=2048,D=1024,H=16,HD=64, scale=32. softmax over batch (B=2) ==
//   P     = sigmoid((Q0K0^T - Q1K1^T)/32)   per head [2048x2048]
//   vals0 = P @ V0 ;  vals1 = colsum(V1) - P @ V1
// fp16 mma.sync m16n8k16; hi/lo split planes:
//   Q/K proj: 3-term | fused score+PV (flash, 32-q-row CTAs, V via
//   ldmatrix.trans d-chunks, warp-pair O combine) | V proj, out: 1-term
// ---------------------------------------------------------------------------

__device__ __align__(128) __half g_xhi[4096 * 1024];
__device__ __align__(128) __half g_xlo[4096 * 1024];
__device__ __align__(128) __half g_wThi[4 * 1024 * 1024];   // [z][n][k]
__device__ __align__(128) __half g_wTlo[4 * 1024 * 1024];
__device__ __align__(128) __half g_Qhi[16 * 2048 * 128];    // [h][s][b*64+d]
__device__ __align__(128) __half g_Qlo[16 * 2048 * 128];
__device__ __align__(128) __half g_Khi[16 * 2048 * 128];    // K1 negated
__device__ __align__(128) __half g_Klo[16 * 2048 * 128];
__device__ __align__(128) __half g_V16[16 * 2048 * 128];    // fp16 V [h][s][b*64+d]
__device__ __align__(128) __half g_Valshi[4096 * 1024];     // [b*2048+q][h*64+d]
__device__ float g_ColPart[16 * 16 * 64];                   // [h][sc][d]

#define SSTR   40                 // halfs per smem row, 32-col chunks (+8 pad)
#define PLANEH (128 * SSTR)       // 5120 halfs / 10240 B

// ---------------------------------------------------------------------------
static __device__ __forceinline__ void cpa16(const __half* dst_smem, const void* src) {
    uint32_t d = (uint32_t)__cvta_generic_to_shared(dst_smem);
    asm volatile("cp.async.cg.shared.global [%0], [%1], 16;" :: "r"(d), "l"(src));
}
static __device__ __forceinline__ void ldm4(uint32_t r[4], const void* p) {
    uint32_t a = (uint32_t)__cvta_generic_to_shared(p);
    asm volatile("ldmatrix.sync.aligned.m8n8.x4.shared.b16 {%0,%1,%2,%3}, [%4];"
                 : "=r"(r[0]), "=r"(r[1]), "=r"(r[2]), "=r"(r[3]) : "r"(a));
}
static __device__ __forceinline__ void ldm4t(uint32_t r[4], const void* p) {
    uint32_t a = (uint32_t)__cvta_generic_to_shared(p);
    asm volatile("ldmatrix.sync.aligned.m8n8.x4.trans.shared.b16 {%0,%1,%2,%3}, [%4];"
                 : "=r"(r[0]), "=r"(r[1]), "=r"(r[2]), "=r"(r[3]) : "r"(a));
}
static __device__ __forceinline__ void mma16816(float c[4], const uint32_t a[4],
                                                uint32_t b0, uint32_t b1) {
    asm volatile(
        "mma.sync.aligned.m16n8k16.row.col.f32.f16.f16.f32 "
        "{%0,%1,%2,%3}, {%4,%5,%6,%7}, {%8,%9}, {%0,%1,%2,%3};"
        : "+f"(c[0]), "+f"(c[1]), "+f"(c[2]), "+f"(c[3])
        : "r"(a[0]), "r"(a[1]), "r"(a[2]), "r"(a[3]), "r"(b0), "r"(b1));
}
static __device__ __forceinline__ void splitstore(__half* hp, __half* lp,
                                                  float v0, float v1) {
    __half h0 = __float2half_rn(v0), h1 = __float2half_rn(v1);
    *(__half2*)hp = __halves2half2(h0, h1);
    *(__half2*)lp = __halves2half2(__float2half_rn(v0 - __half2float(h0)),
                                   __float2half_rn(v1 - __half2float(h1)));
}
// sigmoid(S/32) pair -> packed fp16x2 (lo = first value)
static __device__ __forceinline__ uint32_t sig2(float f0, float f1) {
    const float NK = -0.04508422f;   // -log2(e)/32
    __half2 m2 = __floats2half2_rn(f0 * NK, f1 * NK);
    __half2 P2 = h2rcp(__hadd2(__float2half2_rn(1.0f), h2exp2(m2)));
    return *reinterpret_cast<uint32_t*>(&P2);
}

enum { EPI_QK = 0, EPI_V, EPI_OUT };

// ---------------------------------------------------------------------------
// 128x128 NT GEMM body (device fn), fp16 mma + ldmatrix, NSTG-stage cp.async.
// NTERM=3: Ahi*Bhi + Alo*Bhi + Ahi*Blo ; NTERM=1: A*Bhi
// EPI_V additionally emits deterministic colsum partials of batch-1 V rows.
// ---------------------------------------------------------------------------
template <int KTOT, int NTERM, int EPI, int NSTG>
static __device__ __forceinline__ void gemm_body(float* outp, __half* sm)
{
    const int NA = (NTERM == 3) ? 2 : 1;
    const int NB = (NTERM >= 2) ? 2 : 1;
    const int NT = NA + NB;

    const int tid = threadIdx.x, warp = tid >> 5, lane = tid & 31;
    const int wm = (warp & 3) * 32, wn = (warp >> 2) * 64;
    const int m0 = blockIdx.y * 128, n0 = blockIdx.x * 128, z = blockIdx.z;

    const __half *Ahi, *Alo = nullptr, *Bhi, *Blo = nullptr;
    int lda, ldb;
    if (EPI == EPI_QK) {
        Ahi = g_xhi; Alo = g_xlo; lda = 1024;
        Bhi = g_wThi + (size_t)z * 1048576; Blo = g_wTlo + (size_t)z * 1048576; ldb = 1024;
    } else if (EPI == EPI_V) {
        Ahi = g_xhi; lda = 1024;
        Bhi = g_wThi + (size_t)2 * 1048576; ldb = 1024;
    } else {
        Ahi = g_Valshi; lda = 1024;
        Bhi = g_wThi + (size_t)3 * 1048576; ldb = 1024;
    }

    auto plane = [&](int st, int pl) -> __half* { return sm + (st * NT + pl) * PLANEH; };

    auto load_stage = [&](int ch) {
        const int st = ch % NSTG, k0 = ch * 32;
#pragma unroll
        for (int r = 0; r < 2; ++r) {
            const int idx = tid + r * 256;
            const int row = idx >> 2, col = (idx & 3) * 8;
            cpa16(plane(st, 0) + row * SSTR + col, Ahi + (size_t)(m0 + row) * lda + k0 + col);
            if (NA == 2)
                cpa16(plane(st, 1) + row * SSTR + col, Alo + (size_t)(m0 + row) * lda + k0 + col);
            cpa16(plane(st, NA) + row * SSTR + col, Bhi + (size_t)(n0 + row) * ldb + k0 + col);
            if (NB == 2)
                cpa16(plane(st, NA + 1) + row * SSTR + col, Blo + (size_t)(n0 + row) * ldb + k0 + col);
        }
        asm volatile("cp.async.commit_group;" ::: "memory");
    };

    float c[2][8][4] = {};
    const int nCh = KTOT / 32;
    load_stage(0);
    if (NSTG == 3 && nCh > 1) load_stage(1);

    const int lrow = lane & 15, lkh = (lane >> 4) * 8;

    for (int ch = 0; ch < nCh; ++ch) {
        if (NSTG == 3) {
            if (ch + 1 < nCh) asm volatile("cp.async.wait_group 1;" ::: "memory");
            else              asm volatile("cp.async.wait_group 0;" ::: "memory");
            __syncthreads();
            if (ch + 2 < nCh) load_stage(ch + 2);
        } else {
            if (ch + 1 < nCh) {
                __syncthreads();
                load_stage(ch + 1);
                asm volatile("cp.async.wait_group 1;" ::: "memory");
            } else {
                asm volatile("cp.async.wait_group 0;" ::: "memory");
            }
            __syncthreads();
        }
        const int buf = ch % NSTG;

#pragma unroll
        for (int s = 0; s < 2; ++s) {
            const int ks = s * 16;
            uint32_t a[2][2][4];
#pragma unroll
            for (int pa = 0; pa < NA; ++pa)
#pragma unroll
                for (int mt = 0; mt < 2; ++mt)
                    ldm4(a[pa][mt], plane(buf, pa) + (wm + mt * 16 + lrow) * SSTR + ks + lkh);

            uint32_t bh[4][4];
#pragma unroll
            for (int np = 0; np < 4; ++np) {
                ldm4(bh[np], plane(buf, NA) + (wn + np * 16 + lrow) * SSTR + ks + lkh);
#pragma unroll
                for (int mt = 0; mt < 2; ++mt) {
                    mma16816(c[mt][2 * np],     a[0][mt], bh[np][0], bh[np][2]);
                    mma16816(c[mt][2 * np + 1], a[0][mt], bh[np][1], bh[np][3]);
                }
            }
            if (NA == 2) {
#pragma unroll
                for (int np = 0; np < 4; ++np)
#pragma unroll
                    for (int mt = 0; mt < 2; ++mt) {
                        mma16816(c[mt][2 * np],     a[1][mt], bh[np][0], bh[np][2]);
                        mma16816(c[mt][2 * np + 1], a[1][mt], bh[np][1], bh[np][3]);
                    }
            }
            if (NB == 2) {
#pragma unroll
                for (int np = 0; np < 4; ++np) {
                    uint32_t bl[4];
                    ldm4(bl, plane(buf, NA + 1) + (wn + np * 16 + lrow) * SSTR + ks + lkh);
#pragma unroll
                    for (int mt = 0; mt < 2; ++mt) {
                        mma16816(c[mt][2 * np],     a[0][mt], bl[0], bl[2]);
                        mma16816(c[mt][2 * np + 1], a[0][mt], bl[1], bl[3]);
                    }
                }
            }
        }
    }

    // ---- epilogue: m = m0+wm+mt*16+lane/4+p*8 ; n = n0+wn+nt*8+(lane%4)*2 ----
    float lc[8][2];
    if (EPI == EPI_V)
#pragma unroll
        for (int nt = 0; nt < 8; ++nt) { lc[nt][0] = 0.f; lc[nt][1] = 0.f; }

#pragma unroll
    for (int mt = 0; mt < 2; ++mt)
#pragma unroll
        for (int nt = 0; nt < 8; ++nt)
#pragma unroll
            for (int p = 0; p < 2; ++p) {
                const int m = m0 + wm + mt * 16 + (lane >> 2) + p * 8;
                const int nl = wn + nt * 8 + (lane & 3) * 2;
                float v0 = c[mt][nt][2 * p], v1 = c[mt][nt][2 * p + 1];

                if (EPI == EPI_QK) {
                    const int b = m >> 11, s = m & 2047;
                    const int n = n0 + nl, h = n >> 6, d = n & 63;
                    const size_t base = ((size_t)(h * 2048 + s)) * 128 + b * 64 + d;
                    if (z == 1 && b == 1) { v0 = -v0; v1 = -v1; }
                    __half* Dh = (z == 0) ? g_Qhi : g_Khi;
                    __half* Dl = (z == 0) ? g_Qlo : g_Klo;
                    splitstore(&Dh[base], &Dl[base], v0, v1);
                } else if (EPI == EPI_V) {
                    const int b = m >> 11, s = m & 2047;
                    const int n = n0 + nl, h = n >> 6, d = n & 63;
                    __half2 hv = __floats2half2_rn(v0, v1);
                    *(__half2*)&g_V16[((size_t)(h * 2048 + s)) * 128 + b * 64 + d] = hv;
                    lc[nt][0] += __half2float(__low2half(hv));
                    lc[nt][1] += __half2float(__high2half(hv));
                } else {
                    *(float2*)&outp[(size_t)m * 1024 + n0 + nl] = make_float2(v0, v1);
                }
            }

    // ---- fused colsum partials (batch-1 CTAs only; deterministic order) ----
    if (EPI == EPI_V) {
        float* colbuf = (float*)sm;   // [8 warps][128 cols]
        __syncthreads();
        if (blockIdx.y >= 16) {
#pragma unroll
            for (int nt = 0; nt < 8; ++nt)
#pragma unroll
                for (int j = 0; j < 2; ++j) {
                    float s = lc[nt][j];
                    s += __shfl_xor_sync(0xffffffffu, s, 4);
                    s += __shfl_xor_sync(0xffffffffu, s, 8);
                    s += __shfl_xor_sync(0xffffffffu, s, 16);
                    if ((lane >> 2) == 0)
                        colbuf[warp * 128 + wn + nt * 8 + (lane & 3) * 2 + j] = s;
                }
        }
        __syncthreads();
        if (blockIdx.y >= 16 && tid < 128) {
            const int col = tid, g = col >> 6;
            float s = colbuf[(g * 4 + 0) * 128 + col] + colbuf[(g * 4 + 1) * 128 + col]
                    + colbuf[(g * 4 + 2) * 128 + col] + colbuf[(g * 4 + 3) * 128 + col];
            const int n = n0 + col, h = n >> 6, d = n & 63;
            g_ColPart[((size_t)h * 16 + (blockIdx.y - 16)) * 64 + d] = s;
        }
    }
}

// merged QKV projection: z in {0,1} -> 3-term Q/K, z == 2 -> 1-term V
__global__ __launch_bounds__(256, 2) void qkv_kernel()
{
    extern __shared__ __align__(128) __half sm[];
    if (blockIdx.z == 2) gemm_body<1024, 1, EPI_V, 3>(nullptr, sm);
    else                 gemm_body<1024, 3, EPI_QK, 2>(nullptr, sm);
}

__global__ __launch_bounds__(256, 2) void out_kernel(float* outp)
{
    extern __shared__ __align__(128) __half sm[];
    gemm_body<1024, 1, EPI_OUT, 3>(outp, sm);
}

// ---------------------------------------------------------------------------
// Fused score+PV, 32 q-rows per CTA (fine-grained wave packing).
// 4 warps = 2m x 2n: warp (m16, keys-64). S = 3-term QK^T (Q resident);
// P hoisted to fp16 A-frags once per n-tile; PV over V d-chunks
// [128 keys x 32 d] via ldmatrix.trans; O = warp-pair partial sum (smem).
// Grid (64, 16). smem 82176 B -> occ 2.
// ---------------------------------------------------------------------------
__global__ __launch_bounds__(128, 2) void fattn_kernel()
{
    extern __shared__ __align__(128) __half sm[];
    // Q: [2 planes][4 kc][32 x 40]  (10240 halfs)
    auto qpl = [&](int p, int kc) -> __half* { return sm + (p * 4 + kc) * (32 * SSTR); };
    // K: [2 slots][2 planes][128 x 40] (20480 halfs)
    auto kpl = [&](int slot, int pl) -> __half* { return sm + 10240 + (slot * 2 + pl) * PLANEH; };
    // V: [2 slots][128 keys x 40 (32 d + pad)] (10240 halfs)
    auto vpl = [&](int slot) -> __half* { return sm + 30720 + slot * PLANEH; };
    float* csum = (float*)(sm + 40960);   // [64]

    const int tid = threadIdx.x, warp = tid >> 5, lane = tid & 31;
    const int wm = (warp & 1) * 16, wn = (warp >> 1) * 64;
    const int h = blockIdx.y, m0 = blockIdx.x * 32;

    const __half* Qh = g_Qhi + ((size_t)h * 2048 + m0) * 128;
    const __half* Ql = g_Qlo + ((size_t)h * 2048 + m0) * 128;
    const __half* Kh = g_Khi + (size_t)h * 2048 * 128;
    const __half* Kl = g_Klo + (size_t)h * 2048 * 128;
    const __half* Vs = g_V16 + (size_t)h * 2048 * 128;   // [s][128]

    // group 0: resident Q (both planes, kc-split)
#pragma unroll
    for (int r = 0; r < 4; ++r) {
        const int idx = tid + r * 128;          // 0..511
        const int row = idx >> 4, col = (idx & 15) * 8;
        const int kc = col >> 5, cc = col & 31;
        cpa16(qpl(0, kc) + row * SSTR + cc, Qh + row * 128 + col);
        cpa16(qpl(1, kc) + row * SSTR + cc, Ql + row * 128 + col);
    }
    asm volatile("cp.async.commit_group;" ::: "memory");

    auto issueK = [&](int nt, int kc) {   // K chunk: 128 key-rows x 32 d (hi+lo)
        const int slot = kc & 1, k0 = kc * 32;
#pragma unroll
        for (int r = 0; r < 4; ++r) {
            const int idx = tid + r * 128;
            const int row = idx >> 2, col = (idx & 3) * 8;
            const size_t src = (size_t)(nt * 128 + row) * 128 + k0 + col;
            cpa16(kpl(slot, 0) + row * SSTR + col, Kh + src);
            cpa16(kpl(slot, 1) + row * SSTR + col, Kl + src);
        }
        asm volatile("cp.async.commit_group;" ::: "memory");
    };
    auto issueV = [&](int nt, int vc) {   // V d-chunk: 128 key-rows x 32 d
        const int slot = vc & 1;
#pragma unroll
        for (int r = 0; r < 4; ++r) {
            const int idx = tid + r * 128;
            const int row = idx >> 2, col = (idx & 3) * 8;
            cpa16(vpl(slot) + row * SSTR + col,
                  Vs + (size_t)(nt * 128 + row) * 128 + vc * 32 + col);
        }
        asm volatile("cp.async.commit_group;" ::: "memory");
    };

    issueK(0, 0);
    issueK(0, 1);

    // fused colsum reduction for this head (overlaps with cp.async)
    if (tid < 64) {
        float a = 0.f;
#pragma unroll
        for (int sc = 0; sc < 16; ++sc)
            a += g_ColPart[((size_t)h * 16 + sc) * 64 + tid];
        csum[tid] = a;
    }

    float c[8][4] = {};    // S tile: m16 x keys-64 per warp
    float o[16][4] = {};   // O tile: m16 x d128 per warp (partial over its keys)
    const int lrow = lane & 15, lkh = (lane >> 4) * 8;
    const int qrow = (wm + lrow) * SSTR;

    for (int nt = 0; nt < 16; ++nt) {
        // ---- S phase: 4 d-chunks ----
#pragma unroll
        for (int kc = 0; kc < 4; ++kc) {
            asm volatile("cp.async.wait_group 1;" ::: "memory");
            __syncthreads();
            const int slot = kc & 1;
#pragma unroll
            for (int s = 0; s < 2; ++s) {
                const int ks = s * 16;
                uint32_t a0[4], a1[4];
                ldm4(a0, qpl(0, kc) + qrow + ks + lkh);
                ldm4(a1, qpl(1, kc) + qrow + ks + lkh);
#pragma unroll
                for (int nn = 0; nn < 4; ++nn) {
                    uint32_t bh[4];
                    ldm4(bh, kpl(slot, 0) + (wn + nn * 16 + lrow) * SSTR + ks + lkh);
                    mma16816(c[2 * nn],     a0, bh[0], bh[2]);
                    mma16816(c[2 * nn + 1], a0, bh[1], bh[3]);
                    mma16816(c[2 * nn],     a1, bh[0], bh[2]);
                    mma16816(c[2 * nn + 1], a1, bh[1], bh[3]);
                    uint32_t bl[4];
                    ldm4(bl, kpl(slot, 1) + (wn + nn * 16 + lrow) * SSTR + ks + lkh);
                    mma16816(c[2 * nn],     a0, bl[0], bl[2]);
                    mma16816(c[2 * nn + 1], a0, bl[1], bl[3]);
                }
            }
            __syncthreads();
            if      (kc == 0) issueK(nt, 2);
            else if (kc == 1) issueK(nt, 3);
            else if (kc == 2) issueV(nt, 0);
            else              issueV(nt, 1);
        }

        // ---- P A-frags hoisted once per n-tile ----
        uint32_t pa[4][4];
#pragma unroll
        for (int j = 0; j < 4; ++j) {
            pa[j][0] = sig2(c[2 * j][0],     c[2 * j][1]);
            pa[j][1] = sig2(c[2 * j][2],     c[2 * j][3]);
            pa[j][2] = sig2(c[2 * j + 1][0], c[2 * j + 1][1]);
            pa[j][3] = sig2(c[2 * j + 1][2], c[2 * j + 1][3]);
#pragma unroll
            for (int q = 0; q < 4; ++q) { c[2 * j][q] = 0.f; c[2 * j + 1][q] = 0.f; }
        }

        // ---- PV phase: 4 d-chunks; each warp over its own 64 keys ----
#pragma unroll
        for (int vc = 0; vc < 4; ++vc) {
            if (nt == 15 && vc == 3) asm volatile("cp.async.wait_group 0;" ::: "memory");
            else                     asm volatile("cp.async.wait_group 1;" ::: "memory");
            __syncthreads();
            const int slot = vc & 1;
#pragma unroll
            for (int j = 0; j < 4; ++j) {    // k16 step over warp's keys
#pragma unroll
                for (int t = 0; t < 2; ++t) {  // d16 block within the 32-d chunk
                    uint32_t b[4];
                    ldm4t(b, vpl(slot) + (wn + j * 16 + lrow) * SSTR + t * 16 + lkh);
                    mma16816(o[vc * 4 + 2 * t],     pa[j], b[0], b[1]);
                    mma16816(o[vc * 4 + 2 * t + 1], pa[j], b[2], b[3]);
                }
            }
            __syncthreads();
            if      (vc == 0) issueV(nt, 2);
            else if (vc == 1) issueV(nt, 3);
            else if (vc == 2) { if (nt < 15) issueK(nt + 1, 0); }
            else              { if (nt < 15) issueK(nt + 1, 1); }
        }
    }

    // ---- warp-pair O combine (reuse dead K region as fp32 buffer) ----
    float* obuf = (float*)(sm + 10240);   // [2 m-groups][16 rows][128 d] = 16 KB
    __syncthreads();
    if (wn == 64) {
#pragma unroll
        for (int j = 0; j < 16; ++j)
#pragma unroll
            for (int p = 0; p < 2; ++p) {
                const int row = (lane >> 2) + p * 8;
                const int d = j * 8 + (lane & 3) * 2;
                *(float2*)&obuf[((warp & 1) * 16 + row) * 128 + d] =
                    make_float2(o[j][2 * p], o[j][2 * p + 1]);
            }
    }
    __syncthreads();
    if (wn == 0) {
#pragma unroll
        for (int j = 0; j < 16; ++j)
#pragma unroll
            for (int p = 0; p < 2; ++p) {
                const int row = (lane >> 2) + p * 8;
                const int nl = j * 8 + (lane & 3) * 2;
                float2 t = *(float2*)&obuf[((warp & 1) * 16 + row) * 128 + nl];
                float v0 = o[j][2 * p] + t.x, v1 = o[j][2 * p + 1] + t.y;
                const int m = m0 + wm + row;
                const int b = nl >> 6, d = nl & 63;
                if (b) {
                    v0 = csum[d]     - v0;
                    v1 = csum[d + 1] - v1;
                }
                *(__half2*)&g_Valshi[((size_t)(b * 2048 + m)) * 1024 + h * 64 + d] =
                    __floats2half2_rn(v0, v1);
            }
    }
}

// ---------------------------------------------------------------------------
// merged prep: blocks [0,4096) split x ; blocks [4096,8192) transpose+split W
// ---------------------------------------------------------------------------
__global__ __launch_bounds__(256) void prep_kernel(
    const float* __restrict__ x,
    const float* __restrict__ w0, const float* __restrict__ w1,
    const float* __restrict__ w2, const float* __restrict__ w3)
{
    __shared__ float t[32][33];
    if (blockIdx.x < 4096) {
        const size_t i = ((size_t)blockIdx.x * 256 + threadIdx.x) * 4;
        float4 v = *(const float4*)(x + i);
        splitstore(&g_xhi[i],     &g_xlo[i],     v.x, v.y);
        splitstore(&g_xhi[i + 2], &g_xlo[i + 2], v.z, v.w);
        return;
    }
    const int tb = blockIdx.x - 4096;
    const int z = tb >> 10, r = tb & 1023;
    const int bx = (r & 31) * 32, by = (r >> 5) * 32;
    const float* W = (z == 0) ? w0 : (z == 1) ? w1 : (z == 2) ? w2 : w3;
    const int tx = threadIdx.x & 31, ty8 = threadIdx.x >> 5;
#pragma unroll
    for (int s = 0; s < 4; ++s)
        t[ty8 + s * 8][tx] = W[(size_t)(by + ty8 + s * 8) * 1024 + bx + tx];
    __syncthreads();
    __half* Dh = g_wThi + (size_t)z * 1048576;
    __half* Dl = g_wTlo + (size_t)z * 1048576;
#pragma unroll
    for (int s = 0; s < 4; ++s) {
        const int ty = ty8 + s * 8;
        const float v = t[tx][ty];
        const size_t o = (size_t)(bx + ty) * 1024 + by + tx;
        __half h = __float2half_rn(v);
        Dh[o] = h;
        Dl[o] = __float2half_rn(v - __half2float(h));
    }
}

// ---------------------------------------------------------------------------
extern "C" void kernel_launch(void* const* d_in, const int* in_sizes, int n_in,
                              void* d_out, int out_size)
{
    const float* x  = (const float*)d_in[0];
    const float* wq = (const float*)d_in[1];
    const float* wk = (const float*)d_in[2];
    const float* wv = (const float*)d_in[3];
    const float* wo = (const float*)d_in[4];
    float* out = (float*)d_out;

    const int PB     = PLANEH * 2;                        // 10240 B / plane
    const int SM_QKV = 2 * 4 * PB;                        //  81920 (max of both paths)
    const int SM_1T  = 3 * 2 * PB;                        //  61440 (1-term, 3-stage)
    const int SM_FA  = 40960 * 2 + 256;                   //  82176 (fused attn + csum)

    cudaFuncSetAttribute(qkv_kernel,   cudaFuncAttributeMaxDynamicSharedMemorySize, SM_QKV);
    cudaFuncSetAttribute(out_kernel,   cudaFuncAttributeMaxDynamicSharedMemorySize, SM_1T);
    cudaFuncSetAttribute(fattn_kernel, cudaFuncAttributeMaxDynamicSharedMemorySize, SM_FA);

    prep_kernel<<<8192, 256>>>(x, wq, wk, wv, wo);

    qkv_kernel<<<dim3(8, 32, 3), 256, SM_QKV>>>();

    fattn_kernel<<<dim3(64, 16), 128, SM_FA>>>();

    out_kernel<<<dim3(8, 32, 1), 256, SM_1T>>>(out);
}